// round 1
// baseline (speedup 1.0000x reference)
#include <cuda_runtime.h>
#include <math.h>

#define NR 40000
#define NV 4000
#define ERR 400000
#define EVR 150000
#define ERV 150000
#define FEA 128   // HEADS*H

// ---------------- scratch (device globals: allocation-free rule) ----------------
__device__ float g_x0r[NR*16];
__device__ float g_x0v[NV*16];
__device__ float g_xr[NR*FEA];
__device__ float g_xv[NV*FEA];
__device__ float g_hs0[NR*FEA];
__device__ float g_hs1[NV*FEA];
__device__ float g_hs2[NR*FEA];
__device__ float g_accr[NR*FEA];
__device__ float g_accv[NV*FEA];
__device__ float g_es0[NR*2], g_es1[NV*2], g_es2[NR*2];
__device__ float g_ed0[NR*2], g_ed1[NR*2], g_ed2[NV*2];
__device__ int   g_off0[NR+1], g_off1[NR+1], g_off2[NV+1];
__device__ int   g_cur0[NR],   g_cur1[NR],   g_cur2[NV];
__device__ int   g_srcs0[ERR], g_srcs1[EVR], g_srcs2[ERV];
__device__ float g_wdf[3*256];       // [rel][head][k]
__device__ float g_M[48], g_Mc[6];   // folded edge-attr head
__device__ float g_bns[512];         // BN sums: req [0..256), veh [256..512)
__device__ float g_prs[NR*2], g_prd[NR*2], g_pvs[NV*2], g_pvd[NV*2];

__device__ __forceinline__ float lrelu(float x){ return x >= 0.f ? x : 0.2f*x; }
__device__ __forceinline__ float cleanf(float x){
  if(isnan(x)) return 0.f;
  if(isinf(x)) return x>0.f ? 3.402823466e38f : -3.402823466e38f;
  return x;
}

// ---------------- small utility kernels ----------------
__global__ void k_clean(const float* __restrict__ in, float* __restrict__ out, int n){
  int i=blockIdx.x*blockDim.x+threadIdx.x;
  if(i<n) out[i]=cleanf(in[i]);
}
__global__ void k_zeroi(int* __restrict__ p, int n){
  int i=blockIdx.x*blockDim.x+threadIdx.x; if(i<n) p[i]=0;
}
__global__ void k_zerof(float* __restrict__ p, int n){
  int i=blockIdx.x*blockDim.x+threadIdx.x; if(i<n) p[i]=0.f;
}

// ---------------- CSR build ----------------
__global__ void k_count(const int* __restrict__ dst, int E, int* __restrict__ cnt){
  int e=blockIdx.x*blockDim.x+threadIdx.x;
  if(e<E) atomicAdd(&cnt[dst[e]],1);
}
// single block, 1024 threads: exclusive scan of cnt -> off, also copy -> cur
__global__ void k_scan(const int* __restrict__ cnt, int n, int* __restrict__ off, int* __restrict__ cur){
  __shared__ int part[1024];
  int t=threadIdx.x;
  int chunk=(n+1023)>>10;
  int lo=t*chunk, hi=min(n, lo+chunk);
  int s=0;
  for(int i=lo;i<hi;i++) s+=cnt[i];
  part[t]=s;
  __syncthreads();
  for(int d=1;d<1024;d<<=1){
    int v=(t>=d)? part[t-d]:0;
    __syncthreads();
    if(t>=d) part[t]+=v;
    __syncthreads();
  }
  int base=(t==0)?0:part[t-1];
  for(int i=lo;i<hi;i++){ int c=cnt[i]; off[i]=base; cur[i]=base; base+=c; }
  if(t==1023) off[n]=part[1023];
}
__global__ void k_fill(const int* __restrict__ src, const int* __restrict__ dst, int E,
                       int* __restrict__ cur, int* __restrict__ out_src){
  int e=blockIdx.x*blockDim.x+threadIdx.x;
  if(e<E){ int p=atomicAdd(&cur[dst[e]],1); out_src[p]=src[e]; }
}

// ---------------- GEMM: C[N x 128] = A[N x K] @ W[K x 128], K in {16,128} ----------------
// 8 warps/block, warp-per-row, W chunked 64 rows into SMEM, A row in SMEM. FMA-bound.
__global__ void k_gemm(const float* __restrict__ A, const float* __restrict__ W,
                       float* __restrict__ C, int N, int K){
  __shared__ float Wsh[64*128];
  __shared__ float Ash[8*128];
  int t=threadIdx.x, warp=t>>5, lane=t&31;
  int row=blockIdx.x*8+warp;
  bool valid=row<N;
  if(valid){
    const float4* Ar=(const float4*)(A+(size_t)row*K);
    float4* As=(float4*)(Ash+warp*128);
    for(int i=lane;i<(K>>2);i+=32) As[i]=Ar[i];
  }
  float4 acc=make_float4(0.f,0.f,0.f,0.f);
  for(int kc=0;kc<K;kc+=64){
    int kcn=min(64,K-kc);
    __syncthreads();
    const float4* Wg=(const float4*)(W+(size_t)kc*128);
    float4* Ws4=(float4*)Wsh;
    for(int i=t;i<kcn*32;i+=256) Ws4[i]=Wg[i];
    __syncthreads();
    if(valid){
      const float4* As4=(const float4*)(Ash+warp*128+kc);
      for(int k4=0;k4<(kcn>>2);k4++){
        float4 a=As4[k4];
        float4 w0=((float4*)Wsh)[(4*k4+0)*32+lane];
        float4 w1=((float4*)Wsh)[(4*k4+1)*32+lane];
        float4 w2=((float4*)Wsh)[(4*k4+2)*32+lane];
        float4 w3=((float4*)Wsh)[(4*k4+3)*32+lane];
        acc.x+=a.x*w0.x; acc.y+=a.x*w0.y; acc.z+=a.x*w0.z; acc.w+=a.x*w0.w;
        acc.x+=a.y*w1.x; acc.y+=a.y*w1.y; acc.z+=a.y*w1.z; acc.w+=a.y*w1.w;
        acc.x+=a.z*w2.x; acc.y+=a.z*w2.y; acc.z+=a.z*w2.z; acc.w+=a.z*w2.w;
        acc.x+=a.w*w3.x; acc.y+=a.w*w3.y; acc.z+=a.w*w3.z; acc.w+=a.w*w3.w;
      }
    }
  }
  if(valid) ((float4*)(C+(size_t)row*128))[lane]=acc;
}

// ---------------- fold Wd,a_d -> wdf[rel][head][k] ----------------
__global__ void k_wdf(const float* __restrict__ Wd, const float* __restrict__ ad,
                      int K, float* __restrict__ wdf){
  int t=blockIdx.x*blockDim.x+threadIdx.x;
  if(t>=3*2*K) return;
  int rel=t/(2*K); int rem=t%(2*K); int h=rem/K; int k=rem%K;
  const float* w=Wd+(size_t)rel*K*FEA+(size_t)k*FEA+h*64;
  const float* a=ad+rel*128+h*64;
  float s=0.f;
  for(int j=0;j<64;j++) s+=w[j]*a[j];
  wdf[rel*256+h*128+k]=s;
}

// es[n,h] = dot(hs[n, h*64..], a_s[h])  — warp per node, 16-lane segmented reduce
__global__ void k_es(const float* __restrict__ hs, const float* __restrict__ as,
                     float* __restrict__ es, int N){
  int gid=blockIdx.x*blockDim.x+threadIdx.x;
  int w=gid>>5, lane=gid&31;
  if(w>=N) return;
  float4 h=__ldg((const float4*)(hs+(size_t)w*FEA)+lane);
  float4 a=__ldg(((const float4*)as)+lane);
  float s=h.x*a.x+h.y*a.y+h.z*a.z+h.w*a.w;
  for(int o=8;o>=1;o>>=1) s+=__shfl_xor_sync(0xffffffffu,s,o,16);
  if(lane==0)  es[w*2]=s;
  if(lane==16) es[w*2+1]=s;
}

// ed[n,h] = x[n,:] @ wdf[h,:]  — warp per node
__global__ void k_ed(const float* __restrict__ X, int K, const float* __restrict__ wdf,
                     float* __restrict__ ed, int N){
  int gid=blockIdx.x*blockDim.x+threadIdx.x;
  int w=gid>>5, lane=gid&31;
  if(w>=N) return;
  const float* x=X+(size_t)w*K;
  float s0=0.f, s1=0.f;
  for(int k=lane;k<K;k+=32){ float xv=x[k]; s0+=xv*wdf[k]; s1+=xv*wdf[128+k]; }
  for(int o=16;o>=1;o>>=1){ s0+=__shfl_xor_sync(0xffffffffu,s0,o); s1+=__shfl_xor_sync(0xffffffffu,s1,o); }
  if(lane==0){ ed[w*2]=s0; ed[w*2+1]=s1; }
}

__global__ void k_init(float* __restrict__ acc, const float* __restrict__ b0,
                       const float* __restrict__ b1, int N){
  int i=blockIdx.x*blockDim.x+threadIdx.x;
  if(i<N*FEA){ int f=i&127; float v=b0[f]; if(b1) v+=b1[f]; acc[i]=v; }
}

// CSR gather: per-dst warp softmax + weighted aggregation (no atomics)
__global__ void k_agg(const int* __restrict__ off, const int* __restrict__ srcs,
                      const float* __restrict__ es, const float* __restrict__ ed,
                      const float* __restrict__ hs, float* __restrict__ acc, int Nd){
  int gid=blockIdx.x*blockDim.x+threadIdx.x;
  int w=gid>>5, lane=gid&31;
  if(w>=Nd) return;
  int a0=off[w], a1=off[w+1], deg=a1-a0;
  if(deg==0) return;
  float ed0=ed[w*2], ed1=ed[w*2+1];
  float m0=-1e30f, m1=-1e30f;
  for(int i=lane;i<deg;i+=32){
    int s=srcs[a0+i];
    m0=fmaxf(m0, lrelu(es[s*2]+ed0));
    m1=fmaxf(m1, lrelu(es[s*2+1]+ed1));
  }
  for(int o=16;o>=1;o>>=1){
    m0=fmaxf(m0,__shfl_xor_sync(0xffffffffu,m0,o));
    m1=fmaxf(m1,__shfl_xor_sync(0xffffffffu,m1,o));
  }
  float s0=0.f, s1=0.f;
  for(int i=lane;i<deg;i+=32){
    int s=srcs[a0+i];
    s0+=__expf(lrelu(es[s*2]+ed0)-m0);
    s1+=__expf(lrelu(es[s*2+1]+ed1)-m1);
  }
  for(int o=16;o>=1;o>>=1){
    s0+=__shfl_xor_sync(0xffffffffu,s0,o);
    s1+=__shfl_xor_sync(0xffffffffu,s1,o);
  }
  float inv0=1.f/s0, inv1=1.f/s1;
  bool h1=lane>=16;
  float mh =h1?m1:m0;
  float edh=h1?ed1:ed0;
  float ivh=h1?inv1:inv0;
  int   eso=h1?1:0;
  float4 a=make_float4(0.f,0.f,0.f,0.f);
  for(int j=0;j<deg;j++){
    int s=srcs[a0+j];                          // warp-broadcast load
    float eh=lrelu(es[s*2+eso]+edh);
    float al=__expf(eh-mh)*ivh;
    float4 h=__ldg((const float4*)(hs+(size_t)s*128)+lane);
    a.x+=h.x*al; a.y+=h.y*al; a.z+=h.z*al; a.w+=h.w*al;
  }
  float4* outp=(float4*)(acc+(size_t)w*128)+lane;  // warp owns this row
  float4 o=*outp;
  o.x+=a.x; o.y+=a.y; o.z+=a.z; o.w+=a.w;
  *outp=o;
}

// ---------------- BatchNorm (training-mode batch stats) ----------------
__global__ void k_bnstat(const float* __restrict__ acc, int N, float scale, float* __restrict__ bns){
  int f=threadIdx.x; // 128
  float s=0.f, q=0.f;
  for(int r=blockIdx.x;r<N;r+=gridDim.x){
    float v=scale*acc[(size_t)r*FEA+f]; s+=v; q+=v*v;
  }
  atomicAdd(&bns[f],s); atomicAdd(&bns[128+f],q);
}
__global__ void k_bnapply(const float* __restrict__ acc, int N, float scale,
                          const float* __restrict__ bns,
                          const float* __restrict__ g, const float* __restrict__ b,
                          float* __restrict__ out){
  int i=blockIdx.x*blockDim.x+threadIdx.x;
  if(i>=N*FEA) return;
  int f=i&127;
  float invN=1.f/(float)N;
  float mu =bns[f]*invN;
  float var=bns[128+f]*invN - mu*mu;
  float rs =rsqrtf(var+1e-5f);
  float v=(scale*acc[i]-mu)*rs*g[f]+b[f];
  out[i]=lrelu(v);
}

// ---------------- fold edge-attr head: M = Wp @ Wlin[128:192], Mc = bp@Wlin + blin ----------------
__global__ void k_foldM(const float* __restrict__ Wp, const float* __restrict__ bp,
                        const float* __restrict__ Wlin, const float* __restrict__ blin,
                        float* __restrict__ M, float* __restrict__ Mc){
  int t=threadIdx.x;
  if(t<48){
    int rel=t>>4, rem=t&15, k=rem>>1, o=rem&1;
    float s=0.f;
    for(int j=0;j<64;j++) s+=Wp[rel*512+k*64+j]*Wlin[(128+j)*2+o];
    M[t]=s;
  } else if(t<54){
    int i=t-48, rel=i>>1, o=i&1;
    float s=blin[o];
    for(int j=0;j<64;j++) s+=bp[rel*64+j]*Wlin[(128+j)*2+o];
    Mc[i]=s;
  }
}

// p[n,o] = x[n,:] @ Wlin[base:base+128, o]  — warp per node
__global__ void k_proj(const float* __restrict__ X, const float* __restrict__ Wlin, int base,
                       float* __restrict__ p, int N){
  int gid=blockIdx.x*blockDim.x+threadIdx.x;
  int w=gid>>5, lane=gid&31;
  if(w>=N) return;
  float4 x=__ldg((const float4*)(X+(size_t)w*FEA)+lane);
  const float* wr=Wlin+(base+lane*4)*2;
  float4 wa=__ldg((const float4*)wr);
  float4 wb=__ldg((const float4*)wr+1);
  float s0=x.x*wa.x + x.y*wa.z + x.z*wb.x + x.w*wb.z;
  float s1=x.x*wa.y + x.y*wa.w + x.z*wb.y + x.w*wb.w;
  for(int o=16;o>=1;o>>=1){
    s0+=__shfl_xor_sync(0xffffffffu,s0,o);
    s1+=__shfl_xor_sync(0xffffffffu,s1,o);
  }
  if(lane==0){ p[w*2]=s0; p[w*2+1]=s1; }
}

__global__ void k_edgeout(const int* __restrict__ ei, const float* __restrict__ ea, int E,
                          const float* __restrict__ psrc, const float* __restrict__ pdst,
                          const float* __restrict__ M, const float* __restrict__ Mc,
                          float* __restrict__ out){
  int e=blockIdx.x*blockDim.x+threadIdx.x;
  if(e>=E) return;
  int s=ei[e], d=ei[E+e];
  float l0=psrc[s*2]  +pdst[d*2]  +Mc[0];
  float l1=psrc[s*2+1]+pdst[d*2+1]+Mc[1];
  #pragma unroll
  for(int k=0;k<8;k++){
    float a=cleanf(ea[(size_t)e*8+k]);
    l0+=a*M[k*2]; l1+=a*M[k*2+1];
  }
  float mx=fmaxf(l0,l1);
  float e0=__expf(l0-mx), e1=__expf(l1-mx);
  float inv=1.f/(e0+e1);
  out[(size_t)e*2]=e0*inv; out[(size_t)e*2+1]=e1*inv;
}

// ---------------- host ----------------
#define SYM(var, sym) do{ void* _p; cudaGetSymbolAddress(&_p, sym); var=(decltype(var))_p; }while(0)

extern "C" void kernel_launch(void* const* d_in, const int* in_sizes, int n_in,
                              void* d_out, int out_size){
  (void)in_sizes; (void)n_in; (void)out_size;
  const float* x_req=(const float*)d_in[0];
  const float* x_veh=(const float*)d_in[1];
  const int*   ei_rr=(const int*)d_in[2];
  const int*   ei_vr=(const int*)d_in[3];
  const int*   ei_rv=(const int*)d_in[4];
  const float* ea_rr=(const float*)d_in[5];
  const float* ea_vr=(const float*)d_in[6];
  const float* ea_rv=(const float*)d_in[7];
  const float* Wsrc1=(const float*)d_in[8];
  const float* Wdst1=(const float*)d_in[9];
  const float* asrc1=(const float*)d_in[10];
  const float* adst1=(const float*)d_in[11];
  const float* bias1=(const float*)d_in[12];
  const float* Wsrc2=(const float*)d_in[13];
  const float* Wdst2=(const float*)d_in[14];
  const float* asrc2=(const float*)d_in[15];
  const float* adst2=(const float*)d_in[16];
  const float* bias2=(const float*)d_in[17];
  const float* bn_gamma=(const float*)d_in[18];
  const float* bn_beta =(const float*)d_in[19];
  const float* Wp  =(const float*)d_in[20];
  const float* bp  =(const float*)d_in[21];
  const float* Wlin=(const float*)d_in[22];
  const float* blin=(const float*)d_in[23];
  float* out=(float*)d_out;

  float *x0r,*x0v,*xr,*xv,*hs0,*hs1,*hs2,*accr,*accv;
  float *es0,*es1,*es2,*ed0,*ed1,*ed2,*wdf,*M,*Mc,*bns,*prs,*prd,*pvs,*pvd;
  int *off0,*off1,*off2,*cur0,*cur1,*cur2,*srcs0,*srcs1,*srcs2;
  SYM(x0r,g_x0r); SYM(x0v,g_x0v); SYM(xr,g_xr); SYM(xv,g_xv);
  SYM(hs0,g_hs0); SYM(hs1,g_hs1); SYM(hs2,g_hs2);
  SYM(accr,g_accr); SYM(accv,g_accv);
  SYM(es0,g_es0); SYM(es1,g_es1); SYM(es2,g_es2);
  SYM(ed0,g_ed0); SYM(ed1,g_ed1); SYM(ed2,g_ed2);
  SYM(off0,g_off0); SYM(off1,g_off1); SYM(off2,g_off2);
  SYM(cur0,g_cur0); SYM(cur1,g_cur1); SYM(cur2,g_cur2);
  SYM(srcs0,g_srcs0); SYM(srcs1,g_srcs1); SYM(srcs2,g_srcs2);
  SYM(wdf,g_wdf); SYM(M,g_M); SYM(Mc,g_Mc); SYM(bns,g_bns);
  SYM(prs,g_prs); SYM(prd,g_prd); SYM(pvs,g_pvs); SYM(pvd,g_pvd);

  // ---- CSR build (per relation, by destination) ----
  k_zeroi<<<(NR+255)/256,256>>>(cur0,NR);
  k_zeroi<<<(NR+255)/256,256>>>(cur1,NR);
  k_zeroi<<<(NV+255)/256,256>>>(cur2,NV);
  k_count<<<(ERR+255)/256,256>>>(ei_rr+ERR,ERR,cur0);
  k_count<<<(EVR+255)/256,256>>>(ei_vr+EVR,EVR,cur1);
  k_count<<<(ERV+255)/256,256>>>(ei_rv+ERV,ERV,cur2);
  k_scan<<<1,1024>>>(cur0,NR,off0,cur0);
  k_scan<<<1,1024>>>(cur1,NR,off1,cur1);
  k_scan<<<1,1024>>>(cur2,NV,off2,cur2);
  k_fill<<<(ERR+255)/256,256>>>(ei_rr,ei_rr+ERR,ERR,cur0,srcs0);
  k_fill<<<(EVR+255)/256,256>>>(ei_vr,ei_vr+EVR,EVR,cur1,srcs1);
  k_fill<<<(ERV+255)/256,256>>>(ei_rv,ei_rv+ERV,ERV,cur2,srcs2);

  // ---- nan_to_num inputs ----
  k_clean<<<(NR*16+255)/256,256>>>(x_req,x0r,NR*16);
  k_clean<<<(NV*16+255)/256,256>>>(x_veh,x0v,NV*16);

  // ---- fold edge-attr head (layer-independent) ----
  k_foldM<<<1,64>>>(Wp,bp,Wlin,blin,M,Mc);

  for(int l=0;l<2;l++){
    int K = l?FEA:16;
    const float* Ws=l?Wsrc2:Wsrc1;
    const float* Wd=l?Wdst2:Wdst1;
    const float* as=l?asrc2:asrc1;
    const float* ad=l?adst2:adst1;
    const float* bs=l?bias2:bias1;
    const float* Ar=l?xr:x0r;
    const float* Av=l?xv:x0v;

    int nt=3*2*K;
    k_wdf<<<(nt+255)/256,256>>>(Wd,ad,K,wdf);

    k_gemm<<<(NR+7)/8,256>>>(Ar,Ws+(size_t)0*K*FEA,hs0,NR,K);
    k_gemm<<<(NV+7)/8,256>>>(Av,Ws+(size_t)1*K*FEA,hs1,NV,K);
    k_gemm<<<(NR+7)/8,256>>>(Ar,Ws+(size_t)2*K*FEA,hs2,NR,K);

    k_ed<<<(NR*32+255)/256,256>>>(Ar,K,wdf+0,  ed0,NR);   // rr: dst=req
    k_ed<<<(NR*32+255)/256,256>>>(Ar,K,wdf+256,ed1,NR);   // vr: dst=req
    k_ed<<<(NV*32+255)/256,256>>>(Av,K,wdf+512,ed2,NV);   // rv: dst=veh

    k_es<<<(NR*32+255)/256,256>>>(hs0,as+0,  es0,NR);
    k_es<<<(NV*32+255)/256,256>>>(hs1,as+128,es1,NV);
    k_es<<<(NR*32+255)/256,256>>>(hs2,as+256,es2,NR);

    k_init<<<(NR*FEA+255)/256,256>>>(accr,bs+0,bs+128,NR);   // bias_rr + bias_vr
    k_init<<<(NV*FEA+255)/256,256>>>(accv,bs+256,(const float*)nullptr,NV);

    k_agg<<<(NR*32+255)/256,256>>>(off0,srcs0,es0,ed0,hs0,accr,NR);
    k_agg<<<(NR*32+255)/256,256>>>(off1,srcs1,es1,ed1,hs1,accr,NR);
    k_agg<<<(NV*32+255)/256,256>>>(off2,srcs2,es2,ed2,hs2,accv,NV);

    k_zerof<<<2,256>>>(bns,512);
    k_bnstat<<<256,128>>>(accr,NR,0.5f,bns);
    k_bnstat<<<64,128>>>(accv,NV,1.0f,bns+256);
    k_bnapply<<<(NR*FEA+255)/256,256>>>(accr,NR,0.5f,bns,
        bn_gamma+(l*2+0)*128,bn_beta+(l*2+0)*128,xr);
    k_bnapply<<<(NV*FEA+255)/256,256>>>(accv,NV,1.0f,bns+256,
        bn_gamma+(l*2+1)*128,bn_beta+(l*2+1)*128,xv);
  }

  // ---- final per-edge head (fully folded) ----
  k_proj<<<(NR*32+255)/256,256>>>(xr,Wlin,0,  prs,NR);
  k_proj<<<(NR*32+255)/256,256>>>(xr,Wlin,192,prd,NR);
  k_proj<<<(NV*32+255)/256,256>>>(xv,Wlin,0,  pvs,NV);
  k_proj<<<(NV*32+255)/256,256>>>(xv,Wlin,192,pvd,NV);

  k_edgeout<<<(ERR+255)/256,256>>>(ei_rr,ea_rr,ERR,prs,prd,M,   Mc,  out);
  k_edgeout<<<(EVR+255)/256,256>>>(ei_vr,ea_vr,EVR,pvs,prd,M+16,Mc+2,out+(size_t)ERR*2);
  k_edgeout<<<(ERV+255)/256,256>>>(ei_rv,ea_rv,ERV,prs,pvd,M+32,Mc+4,out+(size_t)(ERR+EVR)*2);
}

// round 2
// speedup vs baseline: 1.7687x; 1.7687x over previous
#include <cuda_runtime.h>
#include <math.h>

#define NR 40000
#define NV 4000
#define ERR 400000
#define EVR 150000
#define ERV 150000
#define FEA 128   // HEADS*H

// ---------------- scratch (device globals: allocation-free rule) ----------------
__device__ float g_x0r[NR*16];
__device__ float g_x0v[NV*16];
__device__ float g_xr[NR*FEA];
__device__ float g_xv[NV*FEA];
__device__ float g_hs0[NR*FEA];
__device__ float g_hs1[NV*FEA];
__device__ float g_hs2[NR*FEA];
__device__ float g_accr[NR*FEA];
__device__ float g_accv[NV*FEA];
__device__ float g_es0[NR*2], g_es1[NV*2], g_es2[NR*2];
__device__ float g_ed0[NR*2], g_ed1[NR*2], g_ed2[NV*2];
__device__ int   g_off0[NR+1], g_off1[NR+1], g_off2[NV+1];
__device__ int   g_cur0[NR],   g_cur1[NR],   g_cur2[NV];
__device__ int   g_srcs0[ERR], g_srcs1[EVR], g_srcs2[ERV];
__device__ float g_wdf[3*256];       // [rel][head][k]
__device__ float g_M[48], g_Mc[6];   // folded edge-attr head
__device__ float g_bns[2*512];       // BN sums per layer
__device__ float g_prs[NR*2], g_prd[NR*2], g_pvs[NV*2], g_pvd[NV*2];

__device__ __forceinline__ float lrelu(float x){ return x >= 0.f ? x : 0.2f*x; }
__device__ __forceinline__ float cleanf(float x){
  if(isnan(x)) return 0.f;
  if(isinf(x)) return x>0.f ? 3.402823466e38f : -3.402823466e38f;
  return x;
}

// ---------------- fused small utilities ----------------
__global__ void k_clean2(const float* __restrict__ a, float* __restrict__ oa,
                         const float* __restrict__ b, float* __restrict__ ob){
  int i=blockIdx.x*blockDim.x+threadIdx.x;
  if(i<NR*16) oa[i]=cleanf(a[i]);
  else if(i<NR*16+NV*16) ob[i-NR*16]=cleanf(b[i-NR*16]);
}
__global__ void k_zero3(int* __restrict__ c0,int* __restrict__ c1,int* __restrict__ c2,
                        float* __restrict__ bns){
  int i=blockIdx.x*blockDim.x+threadIdx.x;
  if(i<NR) c0[i]=0;
  else if(i<2*NR) c1[i-NR]=0;
  else if(i<2*NR+NV) c2[i-2*NR]=0;
  if(i<1024) bns[i]=0.f;
}

// ---------------- CSR build ----------------
__global__ void k_count3(const int* __restrict__ d0,const int* __restrict__ d1,const int* __restrict__ d2,
                         int* __restrict__ c0,int* __restrict__ c1,int* __restrict__ c2){
  int e=blockIdx.x*blockDim.x+threadIdx.x;
  if(e<ERR) atomicAdd(&c0[d0[e]],1);
  else if(e<ERR+EVR) atomicAdd(&c1[d1[e-ERR]],1);
  else if(e<ERR+EVR+ERV) atomicAdd(&c2[d2[e-ERR-EVR]],1);
}
// grid=3 blocks of 1024: blockIdx picks which array to scan
__global__ void k_scan3(int* __restrict__ c0,int* __restrict__ o0,
                        int* __restrict__ c1,int* __restrict__ o1,
                        int* __restrict__ c2,int* __restrict__ o2){
  __shared__ int part[1024];
  int* cnt; int* off; int n;
  if(blockIdx.x==0){cnt=c0;off=o0;n=NR;}
  else if(blockIdx.x==1){cnt=c1;off=o1;n=NR;}
  else {cnt=c2;off=o2;n=NV;}
  int t=threadIdx.x;
  int chunk=(n+1023)>>10;
  int lo=t*chunk, hi=min(n, lo+chunk);
  int s=0;
  for(int i=lo;i<hi;i++) s+=cnt[i];
  part[t]=s;
  __syncthreads();
  for(int d=1;d<1024;d<<=1){
    int v=(t>=d)? part[t-d]:0;
    __syncthreads();
    if(t>=d) part[t]+=v;
    __syncthreads();
  }
  int base=(t==0)?0:part[t-1];
  for(int i=lo;i<hi;i++){ int c=cnt[i]; off[i]=base; cnt[i]=base; base+=c; }
  if(t==1023) off[n]=part[1023];
}
__global__ void k_fill3(const int* __restrict__ rr,const int* __restrict__ vr,const int* __restrict__ rv,
                        int* __restrict__ c0,int* __restrict__ c1,int* __restrict__ c2,
                        int* __restrict__ s0,int* __restrict__ s1,int* __restrict__ s2){
  int e=blockIdx.x*blockDim.x+threadIdx.x;
  if(e<ERR){ int p=atomicAdd(&c0[rr[ERR+e]],1); s0[p]=rr[e]; }
  else if(e<ERR+EVR){ int i=e-ERR; int p=atomicAdd(&c1[vr[EVR+i]],1); s1[p]=vr[i]; }
  else if(e<ERR+EVR+ERV){ int i=e-ERR-EVR; int p=atomicAdd(&c2[rv[ERV+i]],1); s2[p]=rv[i]; }
}

// ---------------- GEMM: C[N x 128] = A[N x K] @ W[K x 128]; fused es epilogue ----------------
// 8 warps/block, 8 rows/warp (64 rows/block). Register-blocked: W SMEM reads amortized 8x.
template<int K>
__global__ void k_gemm2(const float* __restrict__ A, const float* __restrict__ W,
                        float* __restrict__ C, int N,
                        const float* __restrict__ as, float* __restrict__ es){
  constexpr int CH = (K<32)?K:32;                 // W chunk rows
  __shared__ float Wsh[CH*128];                   // <=16KB
  __shared__ float Ash[64*K];                     // <=32KB
  int t=threadIdx.x, warp=t>>5, lane=t&31;
  int row0=blockIdx.x*64;

  // stage A rows (coalesced)
  for(int i=t;i<64*(K/4);i+=256){
    int r=i/(K/4), c=i%(K/4);
    if(row0+r<N) ((float4*)Ash)[i]=((const float4*)(A+(size_t)(row0+r)*K))[c];
  }

  float4 acc[8];
  #pragma unroll
  for(int r=0;r<8;r++) acc[r]=make_float4(0.f,0.f,0.f,0.f);

  for(int kc=0;kc<K;kc+=CH){
    __syncthreads();
    {
      const float4* Wg=(const float4*)(W+(size_t)kc*128);
      float4* Ws4=(float4*)Wsh;
      for(int i=t;i<CH*32;i+=256) Ws4[i]=Wg[i];
    }
    __syncthreads();
    #pragma unroll
    for(int k4=0;k4<CH/4;k4++){
      float4 w0=((float4*)Wsh)[(k4*4+0)*32+lane];
      float4 w1=((float4*)Wsh)[(k4*4+1)*32+lane];
      float4 w2=((float4*)Wsh)[(k4*4+2)*32+lane];
      float4 w3=((float4*)Wsh)[(k4*4+3)*32+lane];
      #pragma unroll
      for(int r=0;r<8;r++){
        float4 a=*(const float4*)(Ash + (warp*8+r)*K + kc + k4*4);
        acc[r].x+=a.x*w0.x; acc[r].y+=a.x*w0.y; acc[r].z+=a.x*w0.z; acc[r].w+=a.x*w0.w;
        acc[r].x+=a.y*w1.x; acc[r].y+=a.y*w1.y; acc[r].z+=a.y*w1.z; acc[r].w+=a.y*w1.w;
        acc[r].x+=a.z*w2.x; acc[r].y+=a.z*w2.y; acc[r].z+=a.z*w2.z; acc[r].w+=a.z*w2.w;
        acc[r].x+=a.w*w3.x; acc[r].y+=a.w*w3.y; acc[r].z+=a.w*w3.z; acc[r].w+=a.w*w3.w;
      }
    }
  }

  // epilogue: store C rows; fused es = per-head dot(acc, a_s)
  float4 av=__ldg((const float4*)as + lane);
  #pragma unroll
  for(int r=0;r<8;r++){
    int row=row0+warp*8+r;
    if(row<N){
      ((float4*)(C+(size_t)row*128))[lane]=acc[r];
      float s=acc[r].x*av.x+acc[r].y*av.y+acc[r].z*av.z+acc[r].w*av.w;
      #pragma unroll
      for(int o=8;o>=1;o>>=1) s+=__shfl_xor_sync(0xffffffffu,s,o,16);
      if(lane==0)  es[row*2]=s;
      if(lane==16) es[row*2+1]=s;
    }
  }
}

// ---------------- fold Wd,a_d -> wdf[rel][head][k] ----------------
__global__ void k_wdf(const float* __restrict__ Wd, const float* __restrict__ ad,
                      int K, float* __restrict__ wdf){
  int t=blockIdx.x*blockDim.x+threadIdx.x;
  if(t>=3*2*K) return;
  int rel=t/(2*K); int rem=t%(2*K); int h=rem/K; int k=rem%K;
  const float* w=Wd+(size_t)rel*K*FEA+(size_t)k*FEA+h*64;
  const float* a=ad+rel*128+h*64;
  float s=0.f;
  for(int j=0;j<64;j++) s+=w[j]*a[j];
  wdf[rel*256+h*128+k]=s;
}

// ed[n,h] = x[n,:] @ wdf[h,:]  — warp per node
__global__ void k_ed(const float* __restrict__ X, int K, const float* __restrict__ wdf,
                     float* __restrict__ ed, int N){
  int gid=blockIdx.x*blockDim.x+threadIdx.x;
  int w=gid>>5, lane=gid&31;
  if(w>=N) return;
  const float* x=X+(size_t)w*K;
  float s0=0.f, s1=0.f;
  for(int k=lane;k<K;k+=32){ float xv=x[k]; s0+=xv*wdf[k]; s1+=xv*wdf[128+k]; }
  for(int o=16;o>=1;o>>=1){ s0+=__shfl_xor_sync(0xffffffffu,s0,o); s1+=__shfl_xor_sync(0xffffffffu,s1,o); }
  if(lane==0){ ed[w*2]=s0; ed[w*2+1]=s1; }
}

// ---------------- softmax-aggregate one relation for node w (warp-collective) ----------------
__device__ __forceinline__ float4 agg_rel(
    const int* __restrict__ off, const int* __restrict__ srcs,
    const float* __restrict__ es, const float* __restrict__ ed,
    const float* __restrict__ hs, int w, int lane, bool h1)
{
  float4 acc=make_float4(0.f,0.f,0.f,0.f);
  int a0=off[w], deg=off[w+1]-a0;
  if(deg==0) return acc;
  float ed0=ed[w*2], ed1=ed[w*2+1];
  if(deg<=128){
    int nc=(deg+31)>>5;
    int   sreg[4];
    float e0[4], e1[4];
    float m0=-1e30f, m1=-1e30f;
    #pragma unroll
    for(int c=0;c<4;c++){
      e0[c]=-1e30f; e1[c]=-1e30f; sreg[c]=0;
      if(c<nc){
        int i=c*32+lane;
        if(i<deg){
          int s=__ldg(&srcs[a0+i]); sreg[c]=s;
          float2 ev=__ldg((const float2*)(es)+s);
          e0[c]=lrelu(ev.x+ed0); e1[c]=lrelu(ev.y+ed1);
          m0=fmaxf(m0,e0[c]); m1=fmaxf(m1,e1[c]);
        }
      }
    }
    #pragma unroll
    for(int o=16;o>=1;o>>=1){
      m0=fmaxf(m0,__shfl_xor_sync(0xffffffffu,m0,o));
      m1=fmaxf(m1,__shfl_xor_sync(0xffffffffu,m1,o));
    }
    float s0=0.f, s1=0.f;
    #pragma unroll
    for(int c=0;c<4;c++){
      e0[c]=__expf(e0[c]-m0);   // invalid lanes: exp(-huge)=0
      e1[c]=__expf(e1[c]-m1);
      s0+=e0[c]; s1+=e1[c];
    }
    #pragma unroll
    for(int o=16;o>=1;o>>=1){
      s0+=__shfl_xor_sync(0xffffffffu,s0,o);
      s1+=__shfl_xor_sync(0xffffffffu,s1,o);
    }
    float inv=1.f/(h1?s1:s0);
    #pragma unroll
    for(int c=0;c<4;c++){
      if(c>=nc) break;
      int n=min(32,deg-c*32);
      for(int j=0;j<n;j++){
        int   sj=__shfl_sync(0xffffffffu,sreg[c],j);
        float aa=__shfl_sync(0xffffffffu,e0[c],j);
        float ab=__shfl_sync(0xffffffffu,e1[c],j);
        float al=(h1?ab:aa)*inv;
        float4 h=__ldg((const float4*)(hs+(size_t)sj*128)+lane);
        acc.x+=h.x*al; acc.y+=h.y*al; acc.z+=h.z*al; acc.w+=h.w*al;
      }
    }
  } else {
    float m0=-1e30f, m1=-1e30f;
    for(int i=lane;i<deg;i+=32){
      int s=__ldg(&srcs[a0+i]);
      float2 ev=__ldg((const float2*)(es)+s);
      m0=fmaxf(m0,lrelu(ev.x+ed0)); m1=fmaxf(m1,lrelu(ev.y+ed1));
    }
    for(int o=16;o>=1;o>>=1){
      m0=fmaxf(m0,__shfl_xor_sync(0xffffffffu,m0,o));
      m1=fmaxf(m1,__shfl_xor_sync(0xffffffffu,m1,o));
    }
    float s0=0.f, s1=0.f;
    for(int i=lane;i<deg;i+=32){
      int s=__ldg(&srcs[a0+i]);
      float2 ev=__ldg((const float2*)(es)+s);
      s0+=__expf(lrelu(ev.x+ed0)-m0);
      s1+=__expf(lrelu(ev.y+ed1)-m1);
    }
    for(int o=16;o>=1;o>>=1){
      s0+=__shfl_xor_sync(0xffffffffu,s0,o);
      s1+=__shfl_xor_sync(0xffffffffu,s1,o);
    }
    float inv=1.f/(h1?s1:s0);
    for(int base=0;base<deg;base+=32){
      int n=min(32,deg-base);
      int sv=0; float ev0=0.f, ev1=0.f;
      if(lane<n){
        sv=__ldg(&srcs[a0+base+lane]);
        float2 ev=__ldg((const float2*)(es)+sv);
        ev0=__expf(lrelu(ev.x+ed0)-m0);
        ev1=__expf(lrelu(ev.y+ed1)-m1);
      }
      for(int j=0;j<n;j++){
        int   sj=__shfl_sync(0xffffffffu,sv,j);
        float aa=__shfl_sync(0xffffffffu,ev0,j);
        float ab=__shfl_sync(0xffffffffu,ev1,j);
        float al=(h1?ab:aa)*inv;
        float4 h=__ldg((const float4*)(hs+(size_t)sj*128)+lane);
        acc.x+=h.x*al; acc.y+=h.y*al; acc.z+=h.z*al; acc.w+=h.w*al;
      }
    }
  }
  return acc;
}

// req nodes: bias_rr + bias_vr + agg(rr) + agg(vr)
__global__ void k_agg_req(const int* __restrict__ off0,const int* __restrict__ s0,
                          const float* __restrict__ es0,const float* __restrict__ ed0,
                          const float* __restrict__ hs0,
                          const int* __restrict__ off1,const int* __restrict__ s1,
                          const float* __restrict__ es1,const float* __restrict__ ed1,
                          const float* __restrict__ hs1,
                          const float* __restrict__ bs, float* __restrict__ acc){
  int gid=blockIdx.x*blockDim.x+threadIdx.x;
  int w=gid>>5, lane=gid&31;
  if(w>=NR) return;
  bool h1=lane>=16;
  float4 a=agg_rel(off0,s0,es0,ed0,hs0,w,lane,h1);
  float4 b=agg_rel(off1,s1,es1,ed1,hs1,w,lane,h1);
  float4 b0=__ldg((const float4*)bs+lane);
  float4 b1=__ldg((const float4*)(bs+128)+lane);
  float4 o;
  o.x=b0.x+b1.x+a.x+b.x; o.y=b0.y+b1.y+a.y+b.y;
  o.z=b0.z+b1.z+a.z+b.z; o.w=b0.w+b1.w+a.w+b.w;
  ((float4*)(acc+(size_t)w*128))[lane]=o;
}
// veh nodes: bias_rv + agg(rv)
__global__ void k_agg_veh(const int* __restrict__ off2,const int* __restrict__ s2,
                          const float* __restrict__ es2,const float* __restrict__ ed2,
                          const float* __restrict__ hs2,
                          const float* __restrict__ bs, float* __restrict__ acc){
  int gid=blockIdx.x*blockDim.x+threadIdx.x;
  int w=gid>>5, lane=gid&31;
  if(w>=NV) return;
  bool h1=lane>=16;
  float4 a=agg_rel(off2,s2,es2,ed2,hs2,w,lane,h1);
  float4 b0=__ldg((const float4*)(bs+256)+lane);
  float4 o;
  o.x=b0.x+a.x; o.y=b0.y+a.y; o.z=b0.z+a.z; o.w=b0.w+a.w;
  ((float4*)(acc+(size_t)w*128))[lane]=o;
}

// ---------------- BatchNorm (training-mode batch stats) — fused both node types ----------------
__global__ void k_bnstat2(const float* __restrict__ accr, const float* __restrict__ accv,
                          float* __restrict__ bns){
  int f=threadIdx.x;
  if(blockIdx.x<256){
    float s=0.f,q=0.f;
    for(int r=blockIdx.x;r<NR;r+=256){ float v=0.5f*accr[(size_t)r*FEA+f]; s+=v; q+=v*v; }
    atomicAdd(&bns[f],s); atomicAdd(&bns[128+f],q);
  } else {
    int b=blockIdx.x-256;
    float s=0.f,q=0.f;
    for(int r=b;r<NV;r+=64){ float v=accv[(size_t)r*FEA+f]; s+=v; q+=v*v; }
    atomicAdd(&bns[256+f],s); atomicAdd(&bns[384+f],q);
  }
}
__global__ void k_bnapply2(const float* __restrict__ accr, const float* __restrict__ accv,
                           const float* __restrict__ bns,
                           const float* __restrict__ gr, const float* __restrict__ br,
                           const float* __restrict__ gv, const float* __restrict__ bv,
                           float* __restrict__ xr, float* __restrict__ xv){
  int i=blockIdx.x*blockDim.x+threadIdx.x;
  if(i<NR*FEA){
    int f=i&127;
    float invN=1.f/(float)NR;
    float mu =bns[f]*invN;
    float var=bns[128+f]*invN - mu*mu;
    float rs =rsqrtf(var+1e-5f);
    xr[i]=lrelu((0.5f*accr[i]-mu)*rs*gr[f]+br[f]);
  } else if(i<NR*FEA+NV*FEA){
    int j=i-NR*FEA; int f=j&127;
    float invN=1.f/(float)NV;
    float mu =bns[256+f]*invN;
    float var=bns[384+f]*invN - mu*mu;
    float rs =rsqrtf(var+1e-5f);
    xv[j]=lrelu((accv[j]-mu)*rs*gv[f]+bv[f]);
  }
}

// ---------------- fold edge-attr head: M = Wp @ Wlin[128:192], Mc = bp@Wlin + blin ----------------
__global__ void k_foldM(const float* __restrict__ Wp, const float* __restrict__ bp,
                        const float* __restrict__ Wlin, const float* __restrict__ blin,
                        float* __restrict__ M, float* __restrict__ Mc){
  int t=threadIdx.x;
  if(t<48){
    int rel=t>>4, rem=t&15, k=rem>>1, o=rem&1;
    float s=0.f;
    for(int j=0;j<64;j++) s+=Wp[rel*512+k*64+j]*Wlin[(128+j)*2+o];
    M[t]=s;
  } else if(t<54){
    int i=t-48, rel=i>>1, o=i&1;
    float s=blin[o];
    for(int j=0;j<64;j++) s+=bp[rel*64+j]*Wlin[(128+j)*2+o];
    Mc[i]=s;
  }
}

// p[n,o] = x[n,:] @ Wlin[base:base+128, o]  — warp per node, 4 fused segments
__global__ void k_proj4(const float* __restrict__ xr, const float* __restrict__ xv,
                        const float* __restrict__ Wlin,
                        float* __restrict__ prs, float* __restrict__ prd,
                        float* __restrict__ pvs, float* __restrict__ pvd){
  int gid=blockIdx.x*blockDim.x+threadIdx.x;
  int w=gid>>5, lane=gid&31;
  const float* X; float* P; int base; int idx;
  if(w<NR){X=xr;P=prs;base=0;idx=w;}
  else if(w<2*NR){X=xr;P=prd;base=192;idx=w-NR;}
  else if(w<2*NR+NV){X=xv;P=pvs;base=0;idx=w-2*NR;}
  else if(w<2*NR+2*NV){X=xv;P=pvd;base=192;idx=w-2*NR-NV;}
  else return;
  float4 x=__ldg((const float4*)(X+(size_t)idx*FEA)+lane);
  const float* wr=Wlin+(base+lane*4)*2;
  float4 wa=__ldg((const float4*)wr);
  float4 wb=__ldg((const float4*)wr+1);
  float s0=x.x*wa.x + x.y*wa.z + x.z*wb.x + x.w*wb.z;
  float s1=x.x*wa.y + x.y*wa.w + x.z*wb.y + x.w*wb.w;
  for(int o=16;o>=1;o>>=1){
    s0+=__shfl_xor_sync(0xffffffffu,s0,o);
    s1+=__shfl_xor_sync(0xffffffffu,s1,o);
  }
  if(lane==0){ P[idx*2]=s0; P[idx*2+1]=s1; }
}

__global__ void k_edgeout(const int* __restrict__ ei, const float* __restrict__ ea, int E,
                          const float* __restrict__ psrc, const float* __restrict__ pdst,
                          const float* __restrict__ M, const float* __restrict__ Mc,
                          float* __restrict__ out){
  int e=blockIdx.x*blockDim.x+threadIdx.x;
  if(e>=E) return;
  int s=ei[e], d=ei[E+e];
  float l0=psrc[s*2]  +pdst[d*2]  +Mc[0];
  float l1=psrc[s*2+1]+pdst[d*2+1]+Mc[1];
  #pragma unroll
  for(int k=0;k<8;k++){
    float a=cleanf(ea[(size_t)e*8+k]);
    l0+=a*M[k*2]; l1+=a*M[k*2+1];
  }
  float mx=fmaxf(l0,l1);
  float e0=__expf(l0-mx), e1=__expf(l1-mx);
  float inv=1.f/(e0+e1);
  out[(size_t)e*2]=e0*inv; out[(size_t)e*2+1]=e1*inv;
}

// ---------------- host ----------------
#define SYM(var, sym) do{ void* _p; cudaGetSymbolAddress(&_p, sym); var=(decltype(var))_p; }while(0)

extern "C" void kernel_launch(void* const* d_in, const int* in_sizes, int n_in,
                              void* d_out, int out_size){
  (void)in_sizes; (void)n_in; (void)out_size;
  const float* x_req=(const float*)d_in[0];
  const float* x_veh=(const float*)d_in[1];
  const int*   ei_rr=(const int*)d_in[2];
  const int*   ei_vr=(const int*)d_in[3];
  const int*   ei_rv=(const int*)d_in[4];
  const float* ea_rr=(const float*)d_in[5];
  const float* ea_vr=(const float*)d_in[6];
  const float* ea_rv=(const float*)d_in[7];
  const float* Wsrc1=(const float*)d_in[8];
  const float* Wdst1=(const float*)d_in[9];
  const float* asrc1=(const float*)d_in[10];
  const float* adst1=(const float*)d_in[11];
  const float* bias1=(const float*)d_in[12];
  const float* Wsrc2=(const float*)d_in[13];
  const float* Wdst2=(const float*)d_in[14];
  const float* asrc2=(const float*)d_in[15];
  const float* adst2=(const float*)d_in[16];
  const float* bias2=(const float*)d_in[17];
  const float* bn_gamma=(const float*)d_in[18];
  const float* bn_beta =(const float*)d_in[19];
  const float* Wp  =(const float*)d_in[20];
  const float* bp  =(const float*)d_in[21];
  const float* Wlin=(const float*)d_in[22];
  const float* blin=(const float*)d_in[23];
  float* out=(float*)d_out;

  float *x0r,*x0v,*xr,*xv,*hs0,*hs1,*hs2,*accr,*accv;
  float *es0,*es1,*es2,*ed0,*ed1,*ed2,*wdf,*M,*Mc,*bns,*prs,*prd,*pvs,*pvd;
  int *off0,*off1,*off2,*cur0,*cur1,*cur2,*srcs0,*srcs1,*srcs2;
  SYM(x0r,g_x0r); SYM(x0v,g_x0v); SYM(xr,g_xr); SYM(xv,g_xv);
  SYM(hs0,g_hs0); SYM(hs1,g_hs1); SYM(hs2,g_hs2);
  SYM(accr,g_accr); SYM(accv,g_accv);
  SYM(es0,g_es0); SYM(es1,g_es1); SYM(es2,g_es2);
  SYM(ed0,g_ed0); SYM(ed1,g_ed1); SYM(ed2,g_ed2);
  SYM(off0,g_off0); SYM(off1,g_off1); SYM(off2,g_off2);
  SYM(cur0,g_cur0); SYM(cur1,g_cur1); SYM(cur2,g_cur2);
  SYM(srcs0,g_srcs0); SYM(srcs1,g_srcs1); SYM(srcs2,g_srcs2);
  SYM(wdf,g_wdf); SYM(M,g_M); SYM(Mc,g_Mc); SYM(bns,g_bns);
  SYM(prs,g_prs); SYM(prd,g_prd); SYM(pvs,g_pvs); SYM(pvd,g_pvd);

  const int ET=ERR+EVR+ERV;

  // ---- zero counters + bns (both layers) ----
  k_zero3<<<(2*NR+NV+255)/256,256>>>(cur0,cur1,cur2,bns);
  // ---- CSR build ----
  k_count3<<<(ET+255)/256,256>>>(ei_rr+ERR,ei_vr+EVR,ei_rv+ERV,cur0,cur1,cur2);
  k_scan3<<<3,1024>>>(cur0,off0,cur1,off1,cur2,off2);
  k_fill3<<<(ET+255)/256,256>>>(ei_rr,ei_vr,ei_rv,cur0,cur1,cur2,srcs0,srcs1,srcs2);
  // ---- nan_to_num inputs ----
  k_clean2<<<((NR+NV)*16+255)/256,256>>>(x_req,x0r,x_veh,x0v);
  // ---- fold edge-attr head ----
  k_foldM<<<1,64>>>(Wp,bp,Wlin,blin,M,Mc);

  for(int l=0;l<2;l++){
    int K = l?FEA:16;
    const float* Ws=l?Wsrc2:Wsrc1;
    const float* Wd=l?Wdst2:Wdst1;
    const float* as=l?asrc2:asrc1;
    const float* ad=l?adst2:adst1;
    const float* bs=l?bias2:bias1;
    const float* Ar=l?xr:x0r;
    const float* Av=l?xv:x0v;
    float* bnsl=bns+l*512;

    int nt=3*2*K;
    k_wdf<<<(nt+255)/256,256>>>(Wd,ad,K,wdf);

    if(l==0){
      k_gemm2<16><<<(NR+63)/64,256>>>(Ar,Ws+(size_t)0*K*FEA,hs0,NR,as+0,  es0);
      k_gemm2<16><<<(NV+63)/64,256>>>(Av,Ws+(size_t)1*K*FEA,hs1,NV,as+128,es1);
      k_gemm2<16><<<(NR+63)/64,256>>>(Ar,Ws+(size_t)2*K*FEA,hs2,NR,as+256,es2);
    } else {
      k_gemm2<128><<<(NR+63)/64,256>>>(Ar,Ws+(size_t)0*K*FEA,hs0,NR,as+0,  es0);
      k_gemm2<128><<<(NV+63)/64,256>>>(Av,Ws+(size_t)1*K*FEA,hs1,NV,as+128,es1);
      k_gemm2<128><<<(NR+63)/64,256>>>(Ar,Ws+(size_t)2*K*FEA,hs2,NR,as+256,es2);
    }

    k_ed<<<(NR*32+255)/256,256>>>(Ar,K,wdf+0,  ed0,NR);   // rr: dst=req
    k_ed<<<(NR*32+255)/256,256>>>(Ar,K,wdf+256,ed1,NR);   // vr: dst=req
    k_ed<<<(NV*32+255)/256,256>>>(Av,K,wdf+512,ed2,NV);   // rv: dst=veh

    k_agg_req<<<(NR*32+255)/256,256>>>(off0,srcs0,es0,ed0,hs0,
                                       off1,srcs1,es1,ed1,hs1,bs,accr);
    k_agg_veh<<<(NV*32+255)/256,256>>>(off2,srcs2,es2,ed2,hs2,bs,accv);

    k_bnstat2<<<320,128>>>(accr,accv,bnsl);
    k_bnapply2<<<((NR+NV)*FEA+255)/256,256>>>(accr,accv,bnsl,
        bn_gamma+(l*2+0)*128,bn_beta+(l*2+0)*128,
        bn_gamma+(l*2+1)*128,bn_beta+(l*2+1)*128, xr,xv);
  }

  // ---- final per-edge head (fully folded) ----
  k_proj4<<<((2*NR+2*NV)*32+255)/256,256>>>(xr,xv,Wlin,prs,prd,pvs,pvd);

  k_edgeout<<<(ERR+255)/256,256>>>(ei_rr,ea_rr,ERR,prs,prd,M,   Mc,  out);
  k_edgeout<<<(EVR+255)/256,256>>>(ei_vr,ea_vr,EVR,pvs,prd,M+16,Mc+2,out+(size_t)ERR*2);
  k_edgeout<<<(ERV+255)/256,256>>>(ei_rv,ea_rv,ERV,prs,pvd,M+32,Mc+4,out+(size_t)(ERR+EVR)*2);
}

// round 3
// speedup vs baseline: 2.0383x; 1.1524x over previous
#include <cuda_runtime.h>
#include <math.h>

#define NR 40000
#define NV 4000
#define ERR 400000
#define EVR 150000
#define ERV 150000
#define ET  (ERR+EVR+ERV)
#define FEA 128   // HEADS*H

// ---------------- scratch (device globals: allocation-free rule) ----------------
__device__ float g_xr[NR*FEA];
__device__ float g_xv[NV*FEA];
__device__ float g_hs0[NR*FEA];
__device__ float g_hs1[NV*FEA];
__device__ float g_hs2[NR*FEA];
__device__ float g_accr[NR*FEA];
__device__ float g_accv[NV*FEA];
__device__ float g_es0[NR*2], g_es1[NV*2], g_es2[NR*2];
__device__ float g_ed0[NR*2], g_ed1[NR*2], g_ed2[NV*2];
__device__ int   g_off0[NR+1], g_off1[NR+1], g_off2[NV+1];
__device__ int   g_cur0[NR],   g_cur1[NR],   g_cur2[NV];
__device__ int   g_srcs0[ERR], g_srcs1[EVR], g_srcs2[ERV];
__device__ float g_wdf[2*768];       // [layer][rel][head][k]
__device__ float g_M[48], g_Mc[6];   // folded edge-attr head
__device__ float g_bns[2*512];       // BN sums per layer
__device__ float g_prs[NR*2], g_prd[NR*2], g_pvs[NV*2], g_pvd[NV*2];

__device__ __forceinline__ float lrelu(float x){ return x >= 0.f ? x : 0.2f*x; }
__device__ __forceinline__ float cleanf(float x){
  if(isnan(x)) return 0.f;
  if(isinf(x)) return x>0.f ? 3.402823466e38f : -3.402823466e38f;
  return x;
}

// packed f32x2 helpers (B300: 2x fp32 FMA throughput, PTX-only)
#define PACK_DUP(out, f) asm("mov.b64 %0, {%1, %1};" : "=l"(out) : "r"(__float_as_uint(f)))
#define FMA2(d, a, b, c) asm("fma.rn.f32x2 %0, %1, %2, %3;" : "=l"(d) : "l"(a), "l"(b), "l"(c))
#define UNPACK2(lo, hi, in) asm("mov.b64 {%0, %1}, %2;" : "=f"(lo), "=f"(hi) : "l"(in))

// ---------------- fused small utilities ----------------
__global__ void k_zero3(int* __restrict__ c0,int* __restrict__ c1,int* __restrict__ c2,
                        float* __restrict__ bns){
  int i=blockIdx.x*blockDim.x+threadIdx.x;
  if(i<NR) c0[i]=0;
  else if(i<2*NR) c1[i-NR]=0;
  else if(i<2*NR+NV) c2[i-2*NR]=0;
  if(i<1024) bns[i]=0.f;
}

// ---------------- CSR build (MLP=4 grid-stride) ----------------
__global__ void k_count3(const int* __restrict__ d0,const int* __restrict__ d1,const int* __restrict__ d2,
                         int* __restrict__ c0,int* __restrict__ c1,int* __restrict__ c2){
  int t=blockIdx.x*blockDim.x+threadIdx.x;
  int nth=gridDim.x*blockDim.x;
  #pragma unroll 4
  for(int e=t;e<ET;e+=nth){
    if(e<ERR) atomicAdd(&c0[d0[e]],1);
    else if(e<ERR+EVR) atomicAdd(&c1[d1[e-ERR]],1);
    else atomicAdd(&c2[d2[e-ERR-EVR]],1);
  }
}
__global__ void k_scan3(int* __restrict__ c0,int* __restrict__ o0,
                        int* __restrict__ c1,int* __restrict__ o1,
                        int* __restrict__ c2,int* __restrict__ o2){
  __shared__ int part[1024];
  int* cnt; int* off; int n;
  if(blockIdx.x==0){cnt=c0;off=o0;n=NR;}
  else if(blockIdx.x==1){cnt=c1;off=o1;n=NR;}
  else {cnt=c2;off=o2;n=NV;}
  int t=threadIdx.x;
  int chunk=(n+1023)>>10;
  int lo=t*chunk, hi=min(n, lo+chunk);
  int s=0;
  for(int i=lo;i<hi;i++) s+=cnt[i];
  part[t]=s;
  __syncthreads();
  for(int d=1;d<1024;d<<=1){
    int v=(t>=d)? part[t-d]:0;
    __syncthreads();
    if(t>=d) part[t]+=v;
    __syncthreads();
  }
  int base=(t==0)?0:part[t-1];
  for(int i=lo;i<hi;i++){ int c=cnt[i]; off[i]=base; cnt[i]=base; base+=c; }
  if(t==1023) off[n]=part[1023];
}
__global__ void k_fill3(const int* __restrict__ rr,const int* __restrict__ vr,const int* __restrict__ rv,
                        int* __restrict__ c0,int* __restrict__ c1,int* __restrict__ c2,
                        int* __restrict__ s0,int* __restrict__ s1,int* __restrict__ s2){
  int t=blockIdx.x*blockDim.x+threadIdx.x;
  int nth=gridDim.x*blockDim.x;
  #pragma unroll 4
  for(int e=t;e<ET;e+=nth){
    if(e<ERR){ int p=atomicAdd(&c0[rr[ERR+e]],1); s0[p]=rr[e]; }
    else if(e<ERR+EVR){ int i=e-ERR; int p=atomicAdd(&c1[vr[EVR+i]],1); s1[p]=vr[i]; }
    else { int i=e-ERR-EVR; int p=atomicAdd(&c2[rv[ERV+i]],1); s2[p]=rv[i]; }
  }
}

// ---------------- prep: wdf (both layers) + folded edge head ----------------
__global__ void k_prep(const float* __restrict__ Wd1,const float* __restrict__ ad1,
                       const float* __restrict__ Wd2,const float* __restrict__ ad2,
                       const float* __restrict__ Wp,const float* __restrict__ bp,
                       const float* __restrict__ Wlin,const float* __restrict__ blin,
                       float* __restrict__ wdf, float* __restrict__ M, float* __restrict__ Mc){
  int t=threadIdx.x;
  if(t<96){
    int rel=t/32, rem=t%32, h=rem/16, k=rem%16;
    const float* w=Wd1+(size_t)rel*16*128 + k*128 + h*64;
    const float* a=ad1+rel*128+h*64;
    float s=0.f; for(int j=0;j<64;j++) s+=w[j]*a[j];
    wdf[rel*256+h*128+k]=s;
  } else if(t<864){
    int i=t-96; int rel=i/256, rem=i%256, h=rem/128, k=rem%128;
    const float* w=Wd2+(size_t)rel*128*128 + k*128 + h*64;
    const float* a=ad2+rel*128+h*64;
    float s=0.f; for(int j=0;j<64;j++) s+=w[j]*a[j];
    wdf[768+rel*256+h*128+k]=s;
  } else if(t<912){
    int q=t-864; int rel=q>>4, rem=q&15, k=rem>>1, o=rem&1;
    float s=0.f;
    for(int j=0;j<64;j++) s+=Wp[rel*512+k*64+j]*Wlin[(128+j)*2+o];
    M[q]=s;
  } else if(t<918){
    int i=t-912, rel=i>>1, o=i&1;
    float s=blin[o];
    for(int j=0;j<64;j++) s+=bp[rel*64+j]*Wlin[(128+j)*2+o];
    Mc[i]=s;
  }
}

// ---------------- GEMM (f32x2): all 3 relations in one launch; fused es + ed + clean ----------------
template<int K, bool CLEAN>
__global__ void k_gemm3(const float* __restrict__ Ar, const float* __restrict__ Av,
                        const float* __restrict__ W,
                        float* __restrict__ hs0, float* __restrict__ hs1, float* __restrict__ hs2,
                        const float* __restrict__ as,
                        float* __restrict__ es0, float* __restrict__ es1, float* __restrict__ es2,
                        const float* __restrict__ wdf,
                        float* __restrict__ ed0, float* __restrict__ ed1, float* __restrict__ ed2){
  constexpr int CH = (K<32)?K:32;
  constexpr int NI = (K+31)/32;
  __shared__ float Wsh[CH*128];
  __shared__ float Ash[64*K];
  int t=threadIdx.x, warp=t>>5, lane=t&31;
  int rel=blockIdx.y;
  const float* A; float* C; float* es; int N;
  const float* wd0=nullptr; const float* wd1=nullptr;
  float* edA=nullptr; float* edB=nullptr;
  if(rel==0){A=Ar;C=hs0;es=es0;N=NR;wd0=wdf;wd1=wdf+256;edA=ed0;edB=ed1;}
  else if(rel==1){A=Av;C=hs1;es=es1;N=NV;wd0=wdf+512;edA=ed2;}
  else {A=Ar;C=hs2;es=es2;N=NR;}
  int row0=blockIdx.x*64;
  if(row0>=N) return;
  const float* Wr = W + (size_t)rel*K*128;

  // stage A (coalesced), optional nan_to_num
  for(int i=t;i<64*(K/4);i+=256){
    int r=i/(K/4), c=i%(K/4);
    if(row0+r<N){
      float4 v=((const float4*)(A+(size_t)(row0+r)*K))[c];
      if(CLEAN){v.x=cleanf(v.x);v.y=cleanf(v.y);v.z=cleanf(v.z);v.w=cleanf(v.w);}
      ((float4*)Ash)[i]=v;
    }
  }

  unsigned long long acc[8][2];
  #pragma unroll
  for(int r=0;r<8;r++){acc[r][0]=0ull;acc[r][1]=0ull;}

  for(int kc=0;kc<K;kc+=CH){
    __syncthreads();
    {
      const float4* Wg=(const float4*)(Wr+(size_t)kc*128);
      float4* Ws4=(float4*)Wsh;
      for(int i=t;i<CH*32;i+=256) Ws4[i]=Wg[i];
    }
    __syncthreads();
    const ulonglong2* W2=(const ulonglong2*)Wsh;
    #pragma unroll
    for(int k4=0;k4<CH/4;k4++){
      ulonglong2 w0=W2[(k4*4+0)*32+lane];
      ulonglong2 w1=W2[(k4*4+1)*32+lane];
      ulonglong2 w2=W2[(k4*4+2)*32+lane];
      ulonglong2 w3=W2[(k4*4+3)*32+lane];
      #pragma unroll
      for(int r=0;r<8;r++){
        float4 a=*(const float4*)(Ash + (warp*8+r)*K + kc + k4*4);
        unsigned long long ax,ay,az,aw;
        PACK_DUP(ax,a.x); PACK_DUP(ay,a.y); PACK_DUP(az,a.z); PACK_DUP(aw,a.w);
        FMA2(acc[r][0],ax,w0.x,acc[r][0]); FMA2(acc[r][1],ax,w0.y,acc[r][1]);
        FMA2(acc[r][0],ay,w1.x,acc[r][0]); FMA2(acc[r][1],ay,w1.y,acc[r][1]);
        FMA2(acc[r][0],az,w2.x,acc[r][0]); FMA2(acc[r][1],az,w2.y,acc[r][1]);
        FMA2(acc[r][0],aw,w3.x,acc[r][0]); FMA2(acc[r][1],aw,w3.y,acc[r][1]);
      }
    }
  }

  // epilogue: store hs; fused es; fused ed dots
  float4 av=__ldg((const float4*)(as+rel*128)+lane);
  float wA0[NI],wA1[NI],wB0[NI],wB1[NI];
  if(edA){
    #pragma unroll
    for(int i=0;i<NI;i++){
      int k=lane+32*i;
      wA0[i]=(k<K)?__ldg(&wd0[k]):0.f;
      wA1[i]=(k<K)?__ldg(&wd0[128+k]):0.f;
      if(edB){ wB0[i]=(k<K)?__ldg(&wd1[k]):0.f; wB1[i]=(k<K)?__ldg(&wd1[128+k]):0.f; }
    }
  }
  #pragma unroll
  for(int r=0;r<8;r++){
    int row=row0+warp*8+r;
    if(row>=N) continue;
    float4 o;
    UNPACK2(o.x,o.y,acc[r][0]);
    UNPACK2(o.z,o.w,acc[r][1]);
    ((float4*)(C+(size_t)row*128))[lane]=o;
    float s=o.x*av.x+o.y*av.y+o.z*av.z+o.w*av.w;
    #pragma unroll
    for(int off=8;off>=1;off>>=1) s+=__shfl_xor_sync(0xffffffffu,s,off,16);
    if(lane==0)  es[row*2]=s;
    if(lane==16) es[row*2+1]=s;
    if(edA){
      float s0=0.f,s1=0.f,s2=0.f,s3=0.f;
      #pragma unroll
      for(int i=0;i<NI;i++){
        int k=lane+32*i;
        if(k<K){
          float xv=Ash[(warp*8+r)*K+k];
          s0+=xv*wA0[i]; s1+=xv*wA1[i];
          if(edB){ s2+=xv*wB0[i]; s3+=xv*wB1[i]; }
        }
      }
      #pragma unroll
      for(int off=16;off>=1;off>>=1){
        s0+=__shfl_xor_sync(0xffffffffu,s0,off);
        s1+=__shfl_xor_sync(0xffffffffu,s1,off);
        if(edB){ s2+=__shfl_xor_sync(0xffffffffu,s2,off); s3+=__shfl_xor_sync(0xffffffffu,s3,off); }
      }
      if(lane==0){
        edA[row*2]=s0; edA[row*2+1]=s1;
        if(edB){ edB[row*2]=s2; edB[row*2+1]=s3; }
      }
    }
  }
}

// ---------------- softmax-aggregate one relation for node w (warp-collective) ----------------
__device__ __forceinline__ float4 agg_rel(
    const int* __restrict__ off, const int* __restrict__ srcs,
    const float* __restrict__ es, const float* __restrict__ ed,
    const float* __restrict__ hs, int w, int lane, bool h1)
{
  float4 acc=make_float4(0.f,0.f,0.f,0.f);
  int a0=off[w], deg=off[w+1]-a0;
  if(deg==0) return acc;
  float ed0=ed[w*2], ed1=ed[w*2+1];
  if(deg<=128){
    int nc=(deg+31)>>5;
    int   sreg[4];
    float e0[4], e1[4];
    float m0=-1e30f, m1=-1e30f;
    #pragma unroll
    for(int c=0;c<4;c++){
      e0[c]=-1e30f; e1[c]=-1e30f; sreg[c]=0;
      if(c<nc){
        int i=c*32+lane;
        if(i<deg){
          int s=__ldg(&srcs[a0+i]); sreg[c]=s;
          float2 ev=__ldg((const float2*)(es)+s);
          e0[c]=lrelu(ev.x+ed0); e1[c]=lrelu(ev.y+ed1);
          m0=fmaxf(m0,e0[c]); m1=fmaxf(m1,e1[c]);
        }
      }
    }
    #pragma unroll
    for(int o=16;o>=1;o>>=1){
      m0=fmaxf(m0,__shfl_xor_sync(0xffffffffu,m0,o));
      m1=fmaxf(m1,__shfl_xor_sync(0xffffffffu,m1,o));
    }
    float s0=0.f, s1=0.f;
    #pragma unroll
    for(int c=0;c<4;c++){
      e0[c]=__expf(e0[c]-m0);
      e1[c]=__expf(e1[c]-m1);
      s0+=e0[c]; s1+=e1[c];
    }
    #pragma unroll
    for(int o=16;o>=1;o>>=1){
      s0+=__shfl_xor_sync(0xffffffffu,s0,o);
      s1+=__shfl_xor_sync(0xffffffffu,s1,o);
    }
    float inv=1.f/(h1?s1:s0);
    #pragma unroll
    for(int c=0;c<4;c++){
      if(c>=nc) break;
      int n=min(32,deg-c*32);
      for(int j=0;j<n;j++){
        int   sj=__shfl_sync(0xffffffffu,sreg[c],j);
        float aa=__shfl_sync(0xffffffffu,e0[c],j);
        float ab=__shfl_sync(0xffffffffu,e1[c],j);
        float al=(h1?ab:aa)*inv;
        float4 h=__ldg((const float4*)(hs+(size_t)sj*128)+lane);
        acc.x+=h.x*al; acc.y+=h.y*al; acc.z+=h.z*al; acc.w+=h.w*al;
      }
    }
  } else {
    float m0=-1e30f, m1=-1e30f;
    for(int i=lane;i<deg;i+=32){
      int s=__ldg(&srcs[a0+i]);
      float2 ev=__ldg((const float2*)(es)+s);
      m0=fmaxf(m0,lrelu(ev.x+ed0)); m1=fmaxf(m1,lrelu(ev.y+ed1));
    }
    for(int o=16;o>=1;o>>=1){
      m0=fmaxf(m0,__shfl_xor_sync(0xffffffffu,m0,o));
      m1=fmaxf(m1,__shfl_xor_sync(0xffffffffu,m1,o));
    }
    float s0=0.f, s1=0.f;
    for(int i=lane;i<deg;i+=32){
      int s=__ldg(&srcs[a0+i]);
      float2 ev=__ldg((const float2*)(es)+s);
      s0+=__expf(lrelu(ev.x+ed0)-m0);
      s1+=__expf(lrelu(ev.y+ed1)-m1);
    }
    for(int o=16;o>=1;o>>=1){
      s0+=__shfl_xor_sync(0xffffffffu,s0,o);
      s1+=__shfl_xor_sync(0xffffffffu,s1,o);
    }
    float inv=1.f/(h1?s1:s0);
    for(int base=0;base<deg;base+=32){
      int n=min(32,deg-base);
      int sv=0; float ev0=0.f, ev1=0.f;
      if(lane<n){
        sv=__ldg(&srcs[a0+base+lane]);
        float2 ev=__ldg((const float2*)(es)+sv);
        ev0=__expf(lrelu(ev.x+ed0)-m0);
        ev1=__expf(lrelu(ev.y+ed1)-m1);
      }
      for(int j=0;j<n;j++){
        int   sj=__shfl_sync(0xffffffffu,sv,j);
        float aa=__shfl_sync(0xffffffffu,ev0,j);
        float ab=__shfl_sync(0xffffffffu,ev1,j);
        float al=(h1?ab:aa)*inv;
        float4 h=__ldg((const float4*)(hs+(size_t)sj*128)+lane);
        acc.x+=h.x*al; acc.y+=h.y*al; acc.z+=h.z*al; acc.w+=h.w*al;
      }
    }
  }
  return acc;
}

// all nodes: req gets rr+vr, veh gets rv
__global__ void k_agg_all(const int* __restrict__ off0,const int* __restrict__ s0,
                          const float* __restrict__ es0,const float* __restrict__ ed0,
                          const float* __restrict__ hs0,
                          const int* __restrict__ off1,const int* __restrict__ s1,
                          const float* __restrict__ es1,const float* __restrict__ ed1,
                          const float* __restrict__ hs1,
                          const int* __restrict__ off2,const int* __restrict__ s2,
                          const float* __restrict__ es2,const float* __restrict__ ed2,
                          const float* __restrict__ hs2,
                          const float* __restrict__ bs,
                          float* __restrict__ accr, float* __restrict__ accv){
  int gid=blockIdx.x*blockDim.x+threadIdx.x;
  int w=gid>>5, lane=gid&31;
  bool h1=lane>=16;
  if(w<NR){
    float4 a=agg_rel(off0,s0,es0,ed0,hs0,w,lane,h1);
    float4 b=agg_rel(off1,s1,es1,ed1,hs1,w,lane,h1);
    float4 b0=__ldg((const float4*)bs+lane);
    float4 b1=__ldg((const float4*)(bs+128)+lane);
    float4 o;
    o.x=b0.x+b1.x+a.x+b.x; o.y=b0.y+b1.y+a.y+b.y;
    o.z=b0.z+b1.z+a.z+b.z; o.w=b0.w+b1.w+a.w+b.w;
    ((float4*)(accr+(size_t)w*128))[lane]=o;
  } else if(w<NR+NV){
    int v=w-NR;
    float4 a=agg_rel(off2,s2,es2,ed2,hs2,v,lane,h1);
    float4 b0=__ldg((const float4*)(bs+256)+lane);
    float4 o;
    o.x=b0.x+a.x; o.y=b0.y+a.y; o.z=b0.z+a.z; o.w=b0.w+a.w;
    ((float4*)(accv+(size_t)v*128))[lane]=o;
  }
}

// ---------------- BatchNorm (training-mode batch stats) ----------------
__global__ void k_bnstat2(const float* __restrict__ accr, const float* __restrict__ accv,
                          float* __restrict__ bns){
  int f=threadIdx.x;
  if(blockIdx.x<256){
    float s=0.f,q=0.f;
    for(int r=blockIdx.x;r<NR;r+=256){ float v=0.5f*accr[(size_t)r*FEA+f]; s+=v; q+=v*v; }
    atomicAdd(&bns[f],s); atomicAdd(&bns[128+f],q);
  } else {
    int b=blockIdx.x-256;
    float s=0.f,q=0.f;
    for(int r=b;r<NV;r+=64){ float v=accv[(size_t)r*FEA+f]; s+=v; q+=v*v; }
    atomicAdd(&bns[256+f],s); atomicAdd(&bns[384+f],q);
  }
}
__global__ void k_bnapply2(const float* __restrict__ accr, const float* __restrict__ accv,
                           const float* __restrict__ bns,
                           const float* __restrict__ gr, const float* __restrict__ br,
                           const float* __restrict__ gv, const float* __restrict__ bv,
                           float* __restrict__ xr, float* __restrict__ xv){
  int i=blockIdx.x*blockDim.x+threadIdx.x;
  if(i<NR*FEA){
    int f=i&127;
    float invN=1.f/(float)NR;
    float mu =bns[f]*invN;
    float var=bns[128+f]*invN - mu*mu;
    float rs =rsqrtf(var+1e-5f);
    xr[i]=lrelu((0.5f*accr[i]-mu)*rs*gr[f]+br[f]);
  } else if(i<NR*FEA+NV*FEA){
    int j=i-NR*FEA; int f=j&127;
    float invN=1.f/(float)NV;
    float mu =bns[256+f]*invN;
    float var=bns[384+f]*invN - mu*mu;
    float rs =rsqrtf(var+1e-5f);
    xv[j]=lrelu((accv[j]-mu)*rs*gv[f]+bv[f]);
  }
}

// ---------------- final head: node projections then per-edge softmax ----------------
__global__ void k_proj4(const float* __restrict__ xr, const float* __restrict__ xv,
                        const float* __restrict__ Wlin,
                        float* __restrict__ prs, float* __restrict__ prd,
                        float* __restrict__ pvs, float* __restrict__ pvd){
  int gid=blockIdx.x*blockDim.x+threadIdx.x;
  int w=gid>>5, lane=gid&31;
  const float* X; float* P; int base; int idx;
  if(w<NR){X=xr;P=prs;base=0;idx=w;}
  else if(w<2*NR){X=xr;P=prd;base=192;idx=w-NR;}
  else if(w<2*NR+NV){X=xv;P=pvs;base=0;idx=w-2*NR;}
  else if(w<2*NR+2*NV){X=xv;P=pvd;base=192;idx=w-2*NR-NV;}
  else return;
  float4 x=__ldg((const float4*)(X+(size_t)idx*FEA)+lane);
  const float* wr=Wlin+(base+lane*4)*2;
  float4 wa=__ldg((const float4*)wr);
  float4 wb=__ldg((const float4*)wr+1);
  float s0=x.x*wa.x + x.y*wa.z + x.z*wb.x + x.w*wb.z;
  float s1=x.x*wa.y + x.y*wa.w + x.z*wb.y + x.w*wb.w;
  for(int o=16;o>=1;o>>=1){
    s0+=__shfl_xor_sync(0xffffffffu,s0,o);
    s1+=__shfl_xor_sync(0xffffffffu,s1,o);
  }
  if(lane==0){ P[idx*2]=s0; P[idx*2+1]=s1; }
}

__global__ void k_edgeout_all(const int* __restrict__ ei_rr, const float* __restrict__ ea_rr,
                              const int* __restrict__ ei_vr, const float* __restrict__ ea_vr,
                              const int* __restrict__ ei_rv, const float* __restrict__ ea_rv,
                              const float* __restrict__ prs, const float* __restrict__ prd,
                              const float* __restrict__ pvs, const float* __restrict__ pvd,
                              const float* __restrict__ M, const float* __restrict__ Mc,
                              float* __restrict__ out){
  int e=blockIdx.x*blockDim.x+threadIdx.x;
  if(e>=ET) return;
  const int* ei; const float* ea; const float* ps; const float* pd;
  const float* Mm; const float* Mcc; int i; int E;
  if(e<ERR){ei=ei_rr;ea=ea_rr;ps=prs;pd=prd;Mm=M;Mcc=Mc;i=e;E=ERR;}
  else if(e<ERR+EVR){ei=ei_vr;ea=ea_vr;ps=pvs;pd=prd;Mm=M+16;Mcc=Mc+2;i=e-ERR;E=EVR;}
  else {ei=ei_rv;ea=ea_rv;ps=prs;pd=pvd;Mm=M+32;Mcc=Mc+4;i=e-ERR-EVR;E=ERV;}
  int s=ei[i], d=ei[E+i];
  float l0=ps[s*2]  +pd[d*2]  +Mcc[0];
  float l1=ps[s*2+1]+pd[d*2+1]+Mcc[1];
  #pragma unroll
  for(int k=0;k<8;k++){
    float a=cleanf(ea[(size_t)i*8+k]);
    l0+=a*Mm[k*2]; l1+=a*Mm[k*2+1];
  }
  float mx=fmaxf(l0,l1);
  float e0=__expf(l0-mx), e1=__expf(l1-mx);
  float inv=1.f/(e0+e1);
  out[(size_t)e*2]=e0*inv; out[(size_t)e*2+1]=e1*inv;
}

// ---------------- host ----------------
#define SYM(var, sym) do{ void* _p; cudaGetSymbolAddress(&_p, sym); var=(decltype(var))_p; }while(0)

extern "C" void kernel_launch(void* const* d_in, const int* in_sizes, int n_in,
                              void* d_out, int out_size){
  (void)in_sizes; (void)n_in; (void)out_size;
  const float* x_req=(const float*)d_in[0];
  const float* x_veh=(const float*)d_in[1];
  const int*   ei_rr=(const int*)d_in[2];
  const int*   ei_vr=(const int*)d_in[3];
  const int*   ei_rv=(const int*)d_in[4];
  const float* ea_rr=(const float*)d_in[5];
  const float* ea_vr=(const float*)d_in[6];
  const float* ea_rv=(const float*)d_in[7];
  const float* Wsrc1=(const float*)d_in[8];
  const float* Wdst1=(const float*)d_in[9];
  const float* asrc1=(const float*)d_in[10];
  const float* adst1=(const float*)d_in[11];
  const float* bias1=(const float*)d_in[12];
  const float* Wsrc2=(const float*)d_in[13];
  const float* Wdst2=(const float*)d_in[14];
  const float* asrc2=(const float*)d_in[15];
  const float* adst2=(const float*)d_in[16];
  const float* bias2=(const float*)d_in[17];
  const float* bn_gamma=(const float*)d_in[18];
  const float* bn_beta =(const float*)d_in[19];
  const float* Wp  =(const float*)d_in[20];
  const float* bp  =(const float*)d_in[21];
  const float* Wlin=(const float*)d_in[22];
  const float* blin=(const float*)d_in[23];
  float* out=(float*)d_out;

  float *xr,*xv,*hs0,*hs1,*hs2,*accr,*accv;
  float *es0,*es1,*es2,*ed0,*ed1,*ed2,*wdf,*M,*Mc,*bns,*prs,*prd,*pvs,*pvd;
  int *off0,*off1,*off2,*cur0,*cur1,*cur2,*srcs0,*srcs1,*srcs2;
  SYM(xr,g_xr); SYM(xv,g_xv);
  SYM(hs0,g_hs0); SYM(hs1,g_hs1); SYM(hs2,g_hs2);
  SYM(accr,g_accr); SYM(accv,g_accv);
  SYM(es0,g_es0); SYM(es1,g_es1); SYM(es2,g_es2);
  SYM(ed0,g_ed0); SYM(ed1,g_ed1); SYM(ed2,g_ed2);
  SYM(off0,g_off0); SYM(off1,g_off1); SYM(off2,g_off2);
  SYM(cur0,g_cur0); SYM(cur1,g_cur1); SYM(cur2,g_cur2);
  SYM(srcs0,g_srcs0); SYM(srcs1,g_srcs1); SYM(srcs2,g_srcs2);
  SYM(wdf,g_wdf); SYM(M,g_M); SYM(Mc,g_Mc); SYM(bns,g_bns);
  SYM(prs,g_prs); SYM(prd,g_prd); SYM(pvs,g_pvs); SYM(pvd,g_pvd);

  // ---- zero counters + bns ----
  k_zero3<<<(2*NR+NV+255)/256,256>>>(cur0,cur1,cur2,bns);
  // ---- CSR build (MLP=4) ----
  k_count3<<<(ET/4+255)/256,256>>>(ei_rr+ERR,ei_vr+EVR,ei_rv+ERV,cur0,cur1,cur2);
  k_scan3<<<3,1024>>>(cur0,off0,cur1,off1,cur2,off2);
  k_fill3<<<(ET/4+255)/256,256>>>(ei_rr,ei_vr,ei_rv,cur0,cur1,cur2,srcs0,srcs1,srcs2);
  // ---- prep: wdf both layers + folded edge head ----
  k_prep<<<1,1024>>>(Wdst1,adst1,Wdst2,adst2,Wp,bp,Wlin,blin,wdf,M,Mc);

  for(int l=0;l<2;l++){
    const float* Ws=l?Wsrc2:Wsrc1;
    const float* as=l?asrc2:asrc1;
    const float* bs=l?bias2:bias1;
    float* bnsl=bns+l*512;
    const float* wdfl=wdf+l*768;

    dim3 grid((NR+63)/64,3);
    if(l==0)
      k_gemm3<16,true ><<<grid,256>>>(x_req,x_veh,Ws,hs0,hs1,hs2,as,es0,es1,es2,wdfl,ed0,ed1,ed2);
    else
      k_gemm3<128,false><<<grid,256>>>(xr,xv,Ws,hs0,hs1,hs2,as,es0,es1,es2,wdfl,ed0,ed1,ed2);

    k_agg_all<<<((NR+NV)*32+255)/256,256>>>(off0,srcs0,es0,ed0,hs0,
                                            off1,srcs1,es1,ed1,hs1,
                                            off2,srcs2,es2,ed2,hs2,bs,accr,accv);

    k_bnstat2<<<320,128>>>(accr,accv,bnsl);
    k_bnapply2<<<((NR+NV)*FEA+255)/256,256>>>(accr,accv,bnsl,
        bn_gamma+(l*2+0)*128,bn_beta+(l*2+0)*128,
        bn_gamma+(l*2+1)*128,bn_beta+(l*2+1)*128, xr,xv);
  }

  // ---- final per-edge head (fully folded) ----
  k_proj4<<<((2*NR+2*NV)*32+255)/256,256>>>(xr,xv,Wlin,prs,prd,pvs,pvd);
  k_edgeout_all<<<(ET+255)/256,256>>>(ei_rr,ea_rr,ei_vr,ea_vr,ei_rv,ea_rv,
                                      prs,prd,pvs,pvd,M,Mc,out);
}